// round 1
// baseline (speedup 1.0000x reference)
#include <cuda_runtime.h>
#include <cstdint>

// ---------------- problem constants ----------------
#define NIMG   8
#define BLK    32         // image block size
#define P_CNT  256        // number of blocks/regions
#define KPSF   64         // PSF size
#define SENS   1024       // sensor dim
#define KB_D   33         // binned kernel taps per axis
#define KB_W   34         // padded width (dx)
#define SB_W   97         // padded smem row width (t in [-32,64] -> 97, odd => conflict-free)

// Binned PSF: [p][phase(ry*2+rx)][dy][dx(pad 34)]
__device__ float g_Kb[P_CNT * 4 * KB_D * KB_W];

__device__ __forceinline__ unsigned long long ffma2(unsigned long long a,
                                                    unsigned long long b,
                                                    unsigned long long c) {
    unsigned long long d;
    asm("fma.rn.f32x2 %0, %1, %2, %3;" : "=l"(d) : "l"(a), "l"(b), "l"(c));
    return d;
}

// ---------------- kernel 0: zero the sensor ----------------
__global__ void zero_kernel(float4* __restrict__ out, int n4) {
    int i = blockIdx.x * blockDim.x + threadIdx.x;
    if (i < n4) out[i] = make_float4(0.f, 0.f, 0.f, 0.f);
}

// ---------------- kernel 1: bin the PSF into 4 phase kernels ----------------
// Kb[p,ry,rx,dy,dx] = sum_{a,c in {0,1}} psf[p][63-ry-2dy+a][63-rx-2dx+c] (valid idx only)
__global__ void binpsf_kernel(const float* __restrict__ psf) {
    int idx = blockIdx.x * blockDim.x + threadIdx.x;
    const int total = P_CNT * 4 * KB_D * KB_W;
    if (idx >= total) return;
    int dx = idx % KB_W;
    int dy = (idx / KB_W) % KB_D;
    int ph = (idx / (KB_W * KB_D)) & 3;
    int p  = idx / (KB_W * KB_D * 4);
    float s = 0.f;
    if (dx < KB_D) {
        int ry = ph >> 1, rx = ph & 1;
        const float* w = psf + (size_t)p * KPSF * KPSF;
        int r0 = 63 - ry - 2 * dy;
        int c0 = 63 - rx - 2 * dx;
        #pragma unroll
        for (int a = 0; a < 2; ++a) {
            int rr = r0 + a;
            if (rr < 0 || rr > 63) continue;
            #pragma unroll
            for (int c = 0; c < 2; ++c) {
                int cc = c0 + c;
                if (cc < 0 || cc > 63) continue;
                s += w[rr * KPSF + cc];
            }
        }
    }
    g_Kb[idx] = s;
}

// ---------------- kernel 2: conv (binned) + splat with atomics ----------------
// grid: 4096 CTAs = p(256) x phase(4) x npair(4). 256 threads.
// thread: 8 consecutive qx outputs x 2 packed images (f32x2), 2 qy values.
__global__ __launch_bounds__(256)
void conv_splat_kernel(const float* __restrict__ imgs,
                       const float* __restrict__ xc,
                       const float* __restrict__ yc,
                       float* __restrict__ out)
{
    const int bid = blockIdx.x;
    const int np  = bid & 3;          // image pair index
    const int ph  = (bid >> 2) & 3;   // phase
    const int p   = bid >> 4;         // region
    const int ry  = ph >> 1, rx = ph & 1;
    const int tid = threadIdx.x;

    __shared__ float2 sKb[KB_D * KB_W];   // (k,k) duplicated for 64-bit broadcast
    __shared__ float2 sB[BLK * SB_W];     // [s][tt] : (img n0, img n1), x zero-padded

    // load phase kernel, duplicated into both f32x2 lanes
    {
        const float* kb = g_Kb + ((size_t)p * 4 + ph) * KB_D * KB_W;
        for (int i = tid; i < KB_D * KB_W; i += 256) {
            float k = kb[i];
            sKb[i] = make_float2(k, k);
        }
    }
    // zero the padded block buffer (padding must be 0)
    for (int i = tid; i < BLK * SB_W; i += 256) sB[i] = make_float2(0.f, 0.f);
    __syncthreads();

    // load the two image blocks interleaved
    const int bh = p & 15, bw = p >> 4;     // p = bw*16 + bh
    {
        const float* pl0 = imgs + ((size_t)(2 * np) * 512 + bh * 32) * 512 + bw * 32;
        const float* pl1 = pl0 + (size_t)512 * 512;
        for (int i = tid; i < BLK * BLK; i += 256) {
            int s = i >> 5, t = i & 31;
            float2 v;
            v.x = pl0[s * 512 + t];
            v.y = pl1[s * 512 + t];
            sB[s * SB_W + 32 + t] = v;
        }
    }
    __syncthreads();

    // splat geometry (all in-bounds for this problem's centers)
    const int ic = 512 + __float2int_rn(xc[p] * 1e6f);
    const int jc = 512 + __float2int_rn(yc[p] * 1e6f);
    const int j0 = jc - 63 + rx;

    const int c   = tid & 7;
    const int qx0 = c << 3;           // 8 outputs along qx
    const int qyb = tid >> 3;         // 0..31

    #pragma unroll
    for (int half = 0; half < 2; ++half) {
        const int qy = qyb + 32 * half;

        unsigned long long acc[8];
        #pragma unroll
        for (int u = 0; u < 8; ++u) acc[u] = 0ULL;

        const int dlo = max(0, qy - 31);
        const int dhi = min(32, qy);
        for (int dy = dlo; dy <= dhi; ++dy) {
            const int s = qy - dy;
            const unsigned long long* row =
                reinterpret_cast<const unsigned long long*>(sB + s * SB_W);
            const unsigned long long* kr =
                reinterpret_cast<const unsigned long long*>(sKb + dy * KB_W);

            // init sliding window: t = qx0+u  (slot = t & 7 = u since qx0 % 8 == 0)
            unsigned long long win[8];
            #pragma unroll
            for (int u = 0; u < 8; ++u) win[u] = row[32 + qx0 + u];

            #pragma unroll
            for (int dx = 0; dx < 33; ++dx) {
                if (dx > 0) win[(-dx) & 7] = row[32 + qx0 - dx];  // new t = qx0-dx
                const unsigned long long k2 = kr[dx];
                #pragma unroll
                for (int u = 0; u < 8; ++u)
                    acc[u] = ffma2(k2, win[(u - dx) & 7], acc[u]);
            }
        }

        // scatter into sensor (phases are disjoint pixels; neighbors overlap -> atomics)
        const int oy = 2 * qy + ry;
        if (oy <= 126) {
            const int irow = ic - 63 + oy;
            float* o0 = out + ((size_t)(2 * np) * SENS + irow) * SENS;
            float* o1 = o0 + (size_t)SENS * SENS;
            #pragma unroll
            for (int u = 0; u < 8; ++u) {
                const int qx = qx0 + u;
                const int ox = 2 * qx + rx;
                if (ox > 126) continue;   // only rx=1, qx=63
                const int j = j0 + 2 * qx;
                float2 v = *reinterpret_cast<float2*>(&acc[u]);
                atomicAdd(o0 + j, v.x);
                atomicAdd(o1 + j, v.y);
            }
        }
    }
}

// ---------------- launch ----------------
extern "C" void kernel_launch(void* const* d_in, const int* in_sizes, int n_in,
                              void* d_out, int out_size) {
    const float* imgs = (const float*)d_in[0];
    const float* psf  = (const float*)d_in[1];
    // d_in[2], d_in[3] = X, Y meshgrids (shape only; SENS hardcoded)
    const float* xc   = (const float*)d_in[4];
    const float* yc   = (const float*)d_in[5];
    float* out = (float*)d_out;

    // zero sensor (poisoned by harness)
    {
        int n4 = out_size / 4;  // 8*1024*1024 / 4
        zero_kernel<<<(n4 + 255) / 256, 256>>>((float4*)out, n4);
    }
    // bin PSFs
    {
        int total = P_CNT * 4 * KB_D * KB_W;
        binpsf_kernel<<<(total + 255) / 256, 256>>>(psf);
    }
    // conv + splat
    conv_splat_kernel<<<P_CNT * 4 * 4, 256>>>(imgs, xc, yc, out);
}